// round 14
// baseline (speedup 1.0000x reference)
#include <cuda_runtime.h>
#include <cuda_bf16.h>
#include <cstdint>

using bf16 = __nv_bfloat16;
typedef signed char s8;

// ---------------------------------------------------------------------------
// Scratch device globals
// ---------------------------------------------------------------------------
static __device__ __align__(128) s8 g_xq1[(size_t)4096*768], g_xq0[(size_t)4096*768];
static __device__ float g_sx[4096];
static __device__ __align__(128) s8 g_wq1[(size_t)2304*768], g_wq0[(size_t)2304*768];
static __device__ float g_swq[2304];
static __device__ __align__(128) s8 g_woq1[(size_t)768*768], g_woq0[(size_t)768*768];
static __device__ float g_swo[768];
static __device__ __align__(128) bf16 g_q_hi [(size_t)24*2048*64], g_q_lo [(size_t)24*2048*64];
static __device__ __align__(128) bf16 g_k_hi [(size_t)24*2048*64], g_k_lo [(size_t)24*2048*64];
static __device__ __align__(128) bf16 g_vt_hi[(size_t)24*64*2048], g_vt_lo[(size_t)24*64*2048];
static __device__ __align__(128) float g_part[2][(size_t)4096*768];   // unnormalized O halves
static __device__ float g_lsum[2][24*2048];                           // partial row sums
static __device__ __align__(128) s8 g_aoq1[(size_t)4096*768], g_aoq0[(size_t)4096*768];
static __device__ float g_sao[4096];

// ---------------------------------------------------------------------------
// Helpers
// ---------------------------------------------------------------------------
__device__ __forceinline__ uint32_t smem_u32(const void* p) {
    return (uint32_t)__cvta_generic_to_shared(p);
}
__device__ __forceinline__ uint32_t sw128(uint32_t o) { return o ^ ((o >> 3) & 0x70); }
__device__ __forceinline__ void cp16(uint32_t dst, const void* src) {
    asm volatile("cp.async.cg.shared.global [%0], [%1], 16;" :: "r"(dst), "l"(src));
}
#define CP_COMMIT() asm volatile("cp.async.commit_group;" ::: "memory")
#define CP_WAIT(n)  asm volatile("cp.async.wait_group %0;" :: "n"(n) : "memory")

__device__ __forceinline__ void ldmx4(uint32_t* r, uint32_t a) {
    asm volatile("ldmatrix.sync.aligned.m8n8.x4.shared.b16 {%0,%1,%2,%3}, [%4];"
                 : "=r"(r[0]), "=r"(r[1]), "=r"(r[2]), "=r"(r[3]) : "r"(a));
}
__device__ __forceinline__ void mma_s8(int* d, const uint32_t* a,
                                       uint32_t b0, uint32_t b1) {
    asm volatile(
        "mma.sync.aligned.m16n8k32.row.col.s32.s8.s8.s32 "
        "{%0,%1,%2,%3}, {%4,%5,%6,%7}, {%8,%9}, {%0,%1,%2,%3};"
        : "+r"(d[0]), "+r"(d[1]), "+r"(d[2]), "+r"(d[3])
        : "r"(a[0]), "r"(a[1]), "r"(a[2]), "r"(a[3]), "r"(b0), "r"(b1));
}
__device__ __forceinline__ void mma_bf16(float* d, const uint32_t* a,
                                         uint32_t b0, uint32_t b1) {
    asm volatile(
        "mma.sync.aligned.m16n8k16.row.col.f32.bf16.bf16.f32 "
        "{%0,%1,%2,%3}, {%4,%5,%6,%7}, {%8,%9}, {%0,%1,%2,%3};"
        : "+f"(d[0]), "+f"(d[1]), "+f"(d[2]), "+f"(d[3])
        : "r"(a[0]), "r"(a[1]), "r"(a[2]), "r"(a[3]), "r"(b0), "r"(b1));
}
__device__ __forceinline__ uint32_t pack2(bf16 a, bf16 b) {
    return (uint32_t)__bfloat16_as_ushort(a) |
           ((uint32_t)__bfloat16_as_ushort(b) << 16);
}
__device__ __forceinline__ uint32_t pack_hilo(float a, float b, uint32_t& lo) {
    bf16 ha = __float2bfloat16(a), hb = __float2bfloat16(b);
    lo = pack2(__float2bfloat16(a - __bfloat162float(ha)),
               __float2bfloat16(b - __bfloat162float(hb)));
    return pack2(ha, hb);
}
__device__ __forceinline__ void quant1(float v, float ip, s8& a1, s8& a0) {
    float x = v * ip;
    float r1 = rintf(x);
    a1 = (s8)(int)r1;
    a0 = (s8)(int)rintf((x - r1) * 254.f);
}
__device__ __forceinline__ float blockmax256(float v, float* red) {
    const int tid = threadIdx.x;
#pragma unroll
    for (int o = 16; o >= 1; o >>= 1)
        v = fmaxf(v, __shfl_xor_sync(0xffffffffu, v, o));
    if ((tid & 31) == 0) red[tid >> 5] = v;
    __syncthreads();
    if (tid == 0) {
        float m = red[0];
#pragma unroll
        for (int w = 1; w < 8; w++) m = fmaxf(m, red[w]);
        red[0] = m;
    }
    __syncthreads();
    return red[0];
}

// ---------------------------------------------------------------------------
// Quantization. quant_inputs merges x / w_qkv / w_o (grid 7168).
// quant_ao combines the two attention partials, normalizes, quantizes.
// ---------------------------------------------------------------------------
__global__ void quant_inputs(const float* __restrict__ x,
                             const float* __restrict__ w_qkv,
                             const float* __restrict__ w_o) {
    __shared__ float red[8];
    const int rb = blockIdx.x, tid = threadIdx.x;
    float v[3]; float mx = 0.f;
    s8 *d1, *d0; float* sc; int r;
    if (rb < 4096) {                      // x rows
        r = rb; d1 = g_xq1; d0 = g_xq0; sc = g_sx;
#pragma unroll
        for (int j = 0; j < 3; j++) {
            v[j] = x[(size_t)r * 768 + tid + j * 256];
            mx = fmaxf(mx, fabsf(v[j]));
        }
    } else if (rb < 6400) {               // w_qkv cols: r = ha*64 + n
        r = rb - 4096; d1 = g_wq1; d0 = g_wq0; sc = g_swq;
#pragma unroll
        for (int j = 0; j < 3; j++) {
            v[j] = w_qkv[((size_t)(r >> 6) * 768 + tid + j * 256) * 64 + (r & 63)];
            mx = fmaxf(mx, fabsf(v[j]));
        }
    } else {                              // w_o cols
        r = rb - 6400; d1 = g_woq1; d0 = g_woq0; sc = g_swo;
#pragma unroll
        for (int j = 0; j < 3; j++) {
            v[j] = w_o[(size_t)(tid + j * 256) * 768 + r];
            mx = fmaxf(mx, fabsf(v[j]));
        }
    }
    mx = fmaxf(blockmax256(mx, red), 1e-20f);
    if (tid == 0) sc[r] = mx * (1.f / 127.f);
    const float ip = 127.f / mx;
#pragma unroll
    for (int j = 0; j < 3; j++) {
        s8 a1, a0; quant1(v[j], ip, a1, a0);
        d1[(size_t)r * 768 + tid + j * 256] = a1;
        d0[(size_t)r * 768 + tid + j * 256] = a0;
    }
}

__global__ void quant_ao() {
    __shared__ float red[8];
    const int r = blockIdx.x, tid = threadIdx.x;   // r = b*2048 + p
    const int b = r >> 11, p = r & 2047;
    float v[3]; float mx = 0.f;
#pragma unroll
    for (int j = 0; j < 3; j++) {
        int c = tid + j * 256;
        int bh = b * 12 + (c >> 6);
        float l = g_lsum[0][bh * 2048 + p] + g_lsum[1][bh * 2048 + p];
        float val = (g_part[0][(size_t)r * 768 + c] + g_part[1][(size_t)r * 768 + c])
                    * __frcp_rn(l);
        v[j] = val;
        mx = fmaxf(mx, fabsf(val));
    }
    mx = fmaxf(blockmax256(mx, red), 1e-20f);
    if (tid == 0) g_sao[r] = mx * (1.f / 127.f);
    const float ip = 127.f / mx;
#pragma unroll
    for (int j = 0; j < 3; j++) {
        s8 a1, a0; quant1(v[j], ip, a1, a0);
        g_aoq1[(size_t)r * 768 + tid + j * 256] = a1;
        g_aoq0[(size_t)r * 768 + tid + j * 256] = a0;
    }
}

// ---------------------------------------------------------------------------
// int8 GEMM core: D[128x64] = A[128x768] * B[64x768]^T (2-stage cp.async)
// ---------------------------------------------------------------------------
#define QSTG 49152u
#define GEMM_SMEM 98304

__device__ __forceinline__ void i8_load_stage(
    uint32_t sb, int st, const s8* __restrict__ A1, const s8* __restrict__ A0,
    const s8* __restrict__ B1, const s8* __restrict__ B0, int kc)
{
    const uint32_t base = sb + (uint32_t)st * QSTG;
    const int tid = threadIdx.x;
#pragma unroll
    for (int j = 0; j < 8; j++) {
        int i = tid + j * 128;
        int r = i >> 3, c = i & 7;
        uint32_t off = sw128((uint32_t)(r * 128 + c * 16));
        cp16(base + off,          A1 + (size_t)r * 768 + kc + c * 16);
        cp16(base + 16384u + off, A0 + (size_t)r * 768 + kc + c * 16);
    }
#pragma unroll
    for (int j = 0; j < 4; j++) {
        int i = tid + j * 128;
        int r = i >> 3, c = i & 7;
        uint32_t off = sw128((uint32_t)(r * 128 + c * 16));
        cp16(base + 32768u + off, B1 + (size_t)r * 768 + kc + c * 16);
        cp16(base + 40960u + off, B0 + (size_t)r * 768 + kc + c * 16);
    }
}

__device__ __forceinline__ void i8_mma_stage(uint32_t sb, int st,
                                             int I11[2][8][4], int Ix[2][8][4])
{
    const int tid = threadIdx.x, wid = tid >> 5, l = tid & 31;
    const int a_r  = l & 15, a_kb = (l >> 4) * 16;
    const int b_n  = (l & 7) + ((l >> 4) & 1) * 8;
    const int b_kb = ((l >> 3) & 1) * 16;
    const int mb = wid * 32;
    const uint32_t base = sb + (uint32_t)st * QSTG;

#pragma unroll
    for (int kb = 0; kb < 4; kb++) {
        uint32_t A1f[2][4], A0f[2][4];
#pragma unroll
        for (int m = 0; m < 2; m++) {
            uint32_t aa = sw128((uint32_t)((mb + m * 16 + a_r) * 128 + kb * 32 + a_kb));
            ldmx4(A1f[m], base + aa);
            ldmx4(A0f[m], base + 16384u + aa);
        }
#pragma unroll
        for (int bn = 0; bn < 4; bn++) {
            uint32_t B1f[4], B0f[4];
            uint32_t ba = sw128((uint32_t)((bn * 16 + b_n) * 128 + kb * 32 + b_kb));
            ldmx4(B1f, base + 32768u + ba);
            ldmx4(B0f, base + 40960u + ba);
#pragma unroll
            for (int m = 0; m < 2; m++) {
                mma_s8(I11[m][2*bn],   A1f[m], B1f[0], B1f[1]);
                mma_s8(Ix [m][2*bn],   A1f[m], B0f[0], B0f[1]);
                mma_s8(Ix [m][2*bn],   A0f[m], B1f[0], B1f[1]);
                mma_s8(I11[m][2*bn+1], A1f[m], B1f[2], B1f[3]);
                mma_s8(Ix [m][2*bn+1], A1f[m], B0f[2], B0f[3]);
                mma_s8(Ix [m][2*bn+1], A0f[m], B1f[2], B1f[3]);
            }
        }
    }
}

__device__ __forceinline__ void i8_gemm(
    uint32_t sb, const s8* A1, const s8* A0, const s8* B1, const s8* B0,
    int I11[2][8][4], int Ix[2][8][4])
{
    i8_load_stage(sb, 0, A1, A0, B1, B0, 0);
    CP_COMMIT();
    for (int kc = 0; kc < 6; kc++) {
        if (kc + 1 < 6) {
            i8_load_stage(sb, (kc + 1) & 1, A1, A0, B1, B0, (kc + 1) * 128);
            CP_COMMIT();
            CP_WAIT(1);
        } else {
            CP_WAIT(0);
        }
        __syncthreads();
        i8_mma_stage(sb, kc & 1, I11, Ix);
        __syncthreads();
    }
}

// ---------------------------------------------------------------------------
// Kernel 1: QKV projection (int8 math, bf16 hi/lo outputs). grid (16,72).
// ---------------------------------------------------------------------------
__global__ __launch_bounds__(128) void qkv_i8_kernel() {
    extern __shared__ char smc[];
    uint32_t sb = smem_u32(smc);
    const int tid = threadIdx.x, wid = tid >> 5, l = tid & 31;
    const int g = l >> 2, t = l & 3;
    const int mb = wid * 32;

    const int m0 = blockIdx.x * 128;
    const int z = blockIdx.y;
    const int a = z / 24, bh = z % 24;
    const int b = bh / 12, h = bh % 12;

    int I11[2][8][4], Ix[2][8][4];
#pragma unroll
    for (int m = 0; m < 2; m++)
#pragma unroll
        for (int nf = 0; nf < 8; nf++)
#pragma unroll
            for (int e = 0; e < 4; e++) { I11[m][nf][e] = 0; Ix[m][nf][e] = 0; }

    i8_gemm(sb,
            g_xq1 + ((size_t)b * 2048 + m0) * 768,
            g_xq0 + ((size_t)b * 2048 + m0) * 768,
            g_wq1 + (size_t)(h * 3 + a) * 64 * 768,
            g_wq0 + (size_t)(h * 3 + a) * 64 * 768, I11, Ix);

    float sxr[2][2], swc[8][2];
#pragma unroll
    for (int m = 0; m < 2; m++)
#pragma unroll
        for (int rh = 0; rh < 2; rh++)
            sxr[m][rh] = g_sx[b * 2048 + m0 + mb + m * 16 + g + rh * 8];
#pragma unroll
    for (int nf = 0; nf < 8; nf++) {
        swc[nf][0] = g_swq[(h * 3 + a) * 64 + nf * 8 + 2 * t];
        swc[nf][1] = g_swq[(h * 3 + a) * 64 + nf * 8 + 2 * t + 1];
    }
    float d[2][8][4];
#pragma unroll
    for (int m = 0; m < 2; m++)
#pragma unroll
        for (int nf = 0; nf < 8; nf++)
#pragma unroll
            for (int e = 0; e < 4; e++) {
                float f = (float)I11[m][nf][e] + (float)Ix[m][nf][e] * (1.f / 254.f);
                d[m][nf][e] = f * sxr[m][e >> 1] * swc[nf][e & 1];
            }

    if (a < 2) {
        const float sc = (a == 0) ? 0.125f : 1.0f;
        bf16* ohb = (a == 0 ? g_q_hi : g_k_hi) + ((size_t)bh * 2048 + m0) * 64;
        bf16* olb = (a == 0 ? g_q_lo : g_k_lo) + ((size_t)bh * 2048 + m0) * 64;
#pragma unroll
        for (int m = 0; m < 2; m++)
#pragma unroll
            for (int rh = 0; rh < 2; rh++) {
                int row = mb + m * 16 + g + rh * 8;
                uint32_t* ph = (uint32_t*)(ohb + (size_t)row * 64);
                uint32_t* pl = (uint32_t*)(olb + (size_t)row * 64);
#pragma unroll
                for (int nf = 0; nf < 8; nf++) {
                    uint32_t lo;
                    uint32_t hi = pack_hilo(d[m][nf][rh*2] * sc,
                                            d[m][nf][rh*2+1] * sc, lo);
                    ph[nf * 4 + t] = hi;
                    pl[nf * 4 + t] = lo;
                }
            }
    } else {
        // V: stage fp32, write transposed [d][p] bf16 hi/lo
        float* Ssm = (float*)smc;   // [128][68]
        __syncthreads();
#pragma unroll
        for (int m = 0; m < 2; m++)
#pragma unroll
            for (int rh = 0; rh < 2; rh++) {
                int row = mb + m * 16 + g + rh * 8;
#pragma unroll
                for (int nf = 0; nf < 8; nf++) {
                    Ssm[row * 68 + nf * 8 + 2 * t]     = d[m][nf][rh * 2];
                    Ssm[row * 68 + nf * 8 + 2 * t + 1] = d[m][nf][rh * 2 + 1];
                }
            }
        __syncthreads();
        for (int idx = tid; idx < 64 * 128; idx += 128) {
            int dd = idx >> 7, p = idx & 127;
            float v = Ssm[p * 68 + dd];
            bf16 hv = __float2bfloat16(v);
            size_t go = ((size_t)bh * 64 + dd) * 2048 + m0 + p;
            g_vt_hi[go] = hv;
            g_vt_lo[go] = __float2bfloat16(v - __bfloat162float(hv));
        }
    }
}

// ---------------------------------------------------------------------------
// Kernel 2: flash attention, bf16 3-term, split-K (z = kv half).
// grid (16, 24, 2), 128 threads. Inner loop identical to R8/R13.
// smem: QH 0 (16K), QL 16384; stages at 32768 + st*32768:
//       KH +0, KL +8192, VH +16384, VL +24576.  total 96K.
// ---------------------------------------------------------------------------
#define ASTAGE_BASE 32768u
#define ASTAGE      32768u
#define ATTN_SMEM   98304
#define KV_TILES    16   // 1024 keys per split

__device__ __forceinline__ void attn_load_stage(uint32_t sb, int st, int bh, int k0) {
    const uint32_t base = sb + ASTAGE_BASE + (uint32_t)st * ASTAGE;
    const int tid = threadIdx.x;
    const bf16* kh = g_k_hi + ((size_t)bh * 2048 + k0) * 64;
    const bf16* kl = g_k_lo + ((size_t)bh * 2048 + k0) * 64;
    const bf16* vh = g_vt_hi + (size_t)bh * 64 * 2048 + k0;
    const bf16* vl = g_vt_lo + (size_t)bh * 64 * 2048 + k0;
#pragma unroll
    for (int j = 0; j < 4; j++) {
        int i = tid + j * 128;
        int r = i >> 3, c = i & 7;
        uint32_t off = sw128((uint32_t)(r * 128 + c * 16));
        cp16(base + off,          kh + (size_t)r * 64 + c * 8);
        cp16(base + 8192u + off,  kl + (size_t)r * 64 + c * 8);
        cp16(base + 16384u + off, vh + (size_t)r * 2048 + c * 8);
        cp16(base + 24576u + off, vl + (size_t)r * 2048 + c * 8);
    }
}

__global__ __launch_bounds__(128) void attn_mma_kernel() {
    extern __shared__ char smc[];
    uint32_t sb = smem_u32(smc);
    const int tid = threadIdx.x, wid = tid >> 5, l = tid & 31;
    const int g = l >> 2, t = l & 3;
    const int a_r  = l & 15;
    const int a_kb = (l >> 4) * 16;
    const int b_n  = (l & 7) + ((l >> 4) & 1) * 8;
    const int b_kb = ((l >> 3) & 1) * 16;
    const int mb = wid * 32;

    const int bh = blockIdx.y;
    const int q0 = blockIdx.x * 128;
    const int zz = blockIdx.z;
    const int kbase = zz * (KV_TILES * 64);

    {
        const bf16* qh = g_q_hi + ((size_t)bh * 2048 + q0) * 64;
        const bf16* ql = g_q_lo + ((size_t)bh * 2048 + q0) * 64;
#pragma unroll
        for (int j = 0; j < 8; j++) {
            int i = tid + j * 128;
            int r = i >> 3, c = i & 7;
            uint32_t off = sw128((uint32_t)(r * 128 + c * 16));
            cp16(sb + off,          qh + (size_t)r * 64 + c * 8);
            cp16(sb + 16384u + off, ql + (size_t)r * 64 + c * 8);
        }
    }
    attn_load_stage(sb, 0, bh, kbase);
    CP_COMMIT();

    float o[2][8][4];
    float lacc[2][2];
#pragma unroll
    for (int m = 0; m < 2; m++) {
        lacc[m][0] = lacc[m][1] = 0.f;
#pragma unroll
        for (int nf = 0; nf < 8; nf++)
#pragma unroll
            for (int e = 0; e < 4; e++) o[m][nf][e] = 0.f;
    }

    for (int kt = 0; kt < KV_TILES; kt++) {
        if (kt + 1 < KV_TILES) {
            attn_load_stage(sb, (kt + 1) & 1, bh, kbase + (kt + 1) * 64);
            CP_COMMIT();
            CP_WAIT(1);
        } else {
            CP_WAIT(0);
        }
        __syncthreads();
        const uint32_t kb = sb + ASTAGE_BASE + (uint32_t)(kt & 1) * ASTAGE;

        float s[2][8][4];
#pragma unroll
        for (int m = 0; m < 2; m++)
#pragma unroll
            for (int nf = 0; nf < 8; nf++)
#pragma unroll
                for (int e = 0; e < 4; e++) s[m][nf][e] = 0.f;

#pragma unroll
        for (int ks = 0; ks < 4; ks++) {
            const int k0b = ks * 32;
            uint32_t Bh[4][4], Bl[4][4];
#pragma unroll
            for (int bn = 0; bn < 4; bn++) {
                uint32_t ba = sw128((uint32_t)((bn * 16 + b_n) * 128 + k0b + b_kb));
                ldmx4(Bh[bn], kb + ba);
                ldmx4(Bl[bn], kb + 8192u + ba);
            }
#pragma unroll
            for (int m = 0; m < 2; m++) {
                uint32_t Ah[4], Al[4];
                uint32_t aa = sw128((uint32_t)((mb + m * 16 + a_r) * 128 + k0b + a_kb));
                ldmx4(Ah, sb + aa);
                ldmx4(Al, sb + 16384u + aa);
#pragma unroll
                for (int bn = 0; bn < 4; bn++) {
                    mma_bf16(s[m][2*bn],   Ah, Bh[bn][0], Bh[bn][1]);
                    mma_bf16(s[m][2*bn],   Ah, Bl[bn][0], Bl[bn][1]);
                    mma_bf16(s[m][2*bn],   Al, Bh[bn][0], Bh[bn][1]);
                    mma_bf16(s[m][2*bn+1], Ah, Bh[bn][2], Bh[bn][3]);
                    mma_bf16(s[m][2*bn+1], Ah, Bl[bn][2], Bl[bn][3]);
                    mma_bf16(s[m][2*bn+1], Al, Bh[bn][2], Bh[bn][3]);
                }
            }
        }

        uint32_t ph[2][4][4], pl[2][4][4];
#pragma unroll
        for (int m = 0; m < 2; m++) {
            float r0 = 0.f, r1 = 0.f;
#pragma unroll
            for (int nf = 0; nf < 8; nf++) {
                s[m][nf][0] = __expf(s[m][nf][0]);
                s[m][nf][1] = __expf(s[m][nf][1]);
                s[m][nf][2] = __expf(s[m][nf][2]);
                s[m][nf][3] = __expf(s[m][nf][3]);
                r0 += s[m][nf][0] + s[m][nf][1];
                r1 += s[m][nf][2] + s[m][nf][3];
            }
            r0 += __shfl_xor_sync(0xffffffffu, r0, 1);
            r0 += __shfl_xor_sync(0xffffffffu, r0, 2);
            r1 += __shfl_xor_sync(0xffffffffu, r1, 1);
            r1 += __shfl_xor_sync(0xffffffffu, r1, 2);
            lacc[m][0] += r0;
            lacc[m][1] += r1;
#pragma unroll
            for (int ks = 0; ks < 4; ks++) {
                ph[m][ks][0] = pack_hilo(s[m][2*ks][0],   s[m][2*ks][1],   pl[m][ks][0]);
                ph[m][ks][1] = pack_hilo(s[m][2*ks][2],   s[m][2*ks][3],   pl[m][ks][1]);
                ph[m][ks][2] = pack_hilo(s[m][2*ks+1][0], s[m][2*ks+1][1], pl[m][ks][2]);
                ph[m][ks][3] = pack_hilo(s[m][2*ks+1][2], s[m][2*ks+1][3], pl[m][ks][3]);
            }
        }

#pragma unroll
        for (int ks = 0; ks < 4; ks++) {
            const int k0b = ks * 32;
            uint32_t Vh[4][4], Vl[4][4];
#pragma unroll
            for (int bn = 0; bn < 4; bn++) {
                uint32_t ba = sw128((uint32_t)((bn * 16 + b_n) * 128 + k0b + b_kb));
                ldmx4(Vh[bn], kb + 16384u + ba);
                ldmx4(Vl[bn], kb + 24576u + ba);
            }
#pragma unroll
            for (int m = 0; m < 2; m++)
#pragma unroll
                for (int bn = 0; bn < 4; bn++) {
                    mma_bf16(o[m][2*bn],   ph[m][ks], Vh[bn][0], Vh[bn][1]);
                    mma_bf16(o[m][2*bn],   ph[m][ks], Vl[bn][0], Vl[bn][1]);
                    mma_bf16(o[m][2*bn],   pl[m][ks], Vh[bn][0], Vh[bn][1]);
                    mma_bf16(o[m][2*bn+1], ph[m][ks], Vh[bn][2], Vh[bn][3]);
                    mma_bf16(o[m][2*bn+1], ph[m][ks], Vl[bn][2], Vl[bn][3]);
                    mma_bf16(o[m][2*bn+1], pl[m][ks], Vh[bn][2], Vh[bn][3]);
                }
        }
        __syncthreads();
    }

    // epilogue: write UNNORMALIZED partial O and row sums
    const int b = bh / 12, h = bh % 12;
#pragma unroll
    for (int m = 0; m < 2; m++)
#pragma unroll
        for (int rh = 0; rh < 2; rh++) {
            int row = mb + m * 16 + g + rh * 8;
            float* op = g_part[zz] + (size_t)(b * 2048 + q0 + row) * 768 + h * 64;
#pragma unroll
            for (int nf = 0; nf < 8; nf++) {
                float2 v = make_float2(o[m][nf][rh*2], o[m][nf][rh*2+1]);
                *(float2*)(op + nf * 8 + 2 * t) = v;
            }
            if (t == 0)
                g_lsum[zz][bh * 2048 + q0 + row] = lacc[m][rh];
        }
}

// ---------------------------------------------------------------------------
// Kernel 3: output projection int8. grid = (32, 12), 128 threads.
// ---------------------------------------------------------------------------
__global__ __launch_bounds__(128) void proj_i8_kernel(float* __restrict__ out) {
    extern __shared__ char smc[];
    uint32_t sb = smem_u32(smc);
    const int tid = threadIdx.x, wid = tid >> 5, l = tid & 31;
    const int g = l >> 2, t = l & 3;
    const int mb = wid * 32;
    const int m0 = blockIdx.x * 128;
    const int n0 = blockIdx.y * 64;

    int I11[2][8][4], Ix[2][8][4];
#pragma unroll
    for (int m = 0; m < 2; m++)
#pragma unroll
        for (int nf = 0; nf < 8; nf++)
#pragma unroll
            for (int e = 0; e < 4; e++) { I11[m][nf][e] = 0; Ix[m][nf][e] = 0; }

    i8_gemm(sb,
            g_aoq1 + (size_t)m0 * 768, g_aoq0 + (size_t)m0 * 768,
            g_woq1 + (size_t)n0 * 768, g_woq0 + (size_t)n0 * 768, I11, Ix);

    float sar[2][2], swc[8][2];
#pragma unroll
    for (int m = 0; m < 2; m++)
#pragma unroll
        for (int rh = 0; rh < 2; rh++)
            sar[m][rh] = g_sao[m0 + mb + m * 16 + g + rh * 8];
#pragma unroll
    for (int nf = 0; nf < 8; nf++) {
        swc[nf][0] = g_swo[n0 + nf * 8 + 2 * t];
        swc[nf][1] = g_swo[n0 + nf * 8 + 2 * t + 1];
    }
#pragma unroll
    for (int m = 0; m < 2; m++)
#pragma unroll
        for (int rh = 0; rh < 2; rh++) {
            int row = mb + m * 16 + g + rh * 8;
            float* op = out + (size_t)(m0 + row) * 768 + n0;
#pragma unroll
            for (int nf = 0; nf < 8; nf++) {
                float f0 = (float)I11[m][nf][rh*2]   + (float)Ix[m][nf][rh*2]   * (1.f/254.f);
                float f1 = (float)I11[m][nf][rh*2+1] + (float)Ix[m][nf][rh*2+1] * (1.f/254.f);
                float2 v = make_float2(f0 * sar[m][rh] * swc[nf][0],
                                       f1 * sar[m][rh] * swc[nf][1]);
                *(float2*)(op + nf * 8 + 2 * t) = v;
            }
        }
}

// ---------------------------------------------------------------------------
extern "C" void kernel_launch(void* const* d_in, const int* in_sizes, int n_in,
                              void* d_out, int out_size)
{
    const float* x = nullptr;
    const float* w_qkv = nullptr;
    const float* w_o = nullptr;
    for (int i = 0; i < n_in; i++) {
        if (in_sizes[i] == 3145728)      x     = (const float*)d_in[i];
        else if (in_sizes[i] == 1769472) w_qkv = (const float*)d_in[i];
        else if (in_sizes[i] == 589824)  w_o   = (const float*)d_in[i];
    }
    float* out = (float*)d_out;

    cudaFuncSetAttribute(qkv_i8_kernel,
                         cudaFuncAttributeMaxDynamicSharedMemorySize, GEMM_SMEM);
    cudaFuncSetAttribute(attn_mma_kernel,
                         cudaFuncAttributeMaxDynamicSharedMemorySize, ATTN_SMEM);
    cudaFuncSetAttribute(proj_i8_kernel,
                         cudaFuncAttributeMaxDynamicSharedMemorySize, GEMM_SMEM);

    quant_inputs<<<7168, 256>>>(x, w_qkv, w_o);
    qkv_i8_kernel<<<dim3(16, 72), 128, GEMM_SMEM>>>();
    attn_mma_kernel<<<dim3(16, 24, 2), 128, ATTN_SMEM>>>();
    quant_ao<<<4096, 256>>>();
    proj_i8_kernel<<<dim3(32, 12), 128, GEMM_SMEM>>>(out);
}

// round 15
// speedup vs baseline: 1.0505x; 1.0505x over previous
#include <cuda_runtime.h>
#include <cuda_bf16.h>
#include <cstdint>

using bf16 = __nv_bfloat16;
typedef signed char s8;

// ---------------------------------------------------------------------------
// Scratch device globals
// ---------------------------------------------------------------------------
static __device__ __align__(128) s8 g_xq1[(size_t)4096*768], g_xq0[(size_t)4096*768];
static __device__ float g_sx[4096];
static __device__ __align__(128) s8 g_wq1[(size_t)2304*768], g_wq0[(size_t)2304*768];
static __device__ float g_swq[2304];
static __device__ __align__(128) s8 g_woq1[(size_t)768*768], g_woq0[(size_t)768*768];
static __device__ float g_swo[768];
static __device__ __align__(128) bf16 g_q_hi [(size_t)24*2048*64], g_q_lo [(size_t)24*2048*64];
static __device__ __align__(128) bf16 g_k_hi [(size_t)24*2048*64], g_k_lo [(size_t)24*2048*64];
static __device__ __align__(128) bf16 g_vt_hi[(size_t)24*64*2048], g_vt_lo[(size_t)24*64*2048];
static __device__ __align__(128) float g_aof[(size_t)4096*768];
static __device__ __align__(128) s8 g_aoq1[(size_t)4096*768], g_aoq0[(size_t)4096*768];
static __device__ float g_sao[4096];

// ---------------------------------------------------------------------------
// Helpers
// ---------------------------------------------------------------------------
__device__ __forceinline__ uint32_t smem_u32(const void* p) {
    return (uint32_t)__cvta_generic_to_shared(p);
}
__device__ __forceinline__ uint32_t sw128(uint32_t o) { return o ^ ((o >> 3) & 0x70); }
__device__ __forceinline__ void cp16(uint32_t dst, const void* src) {
    asm volatile("cp.async.cg.shared.global [%0], [%1], 16;" :: "r"(dst), "l"(src));
}
#define CP_COMMIT() asm volatile("cp.async.commit_group;" ::: "memory")
#define CP_WAIT(n)  asm volatile("cp.async.wait_group %0;" :: "n"(n) : "memory")

__device__ __forceinline__ void ldmx4(uint32_t* r, uint32_t a) {
    asm volatile("ldmatrix.sync.aligned.m8n8.x4.shared.b16 {%0,%1,%2,%3}, [%4];"
                 : "=r"(r[0]), "=r"(r[1]), "=r"(r[2]), "=r"(r[3]) : "r"(a));
}
__device__ __forceinline__ void mma_s8(int* d, const uint32_t* a,
                                       uint32_t b0, uint32_t b1) {
    asm volatile(
        "mma.sync.aligned.m16n8k32.row.col.s32.s8.s8.s32 "
        "{%0,%1,%2,%3}, {%4,%5,%6,%7}, {%8,%9}, {%0,%1,%2,%3};"
        : "+r"(d[0]), "+r"(d[1]), "+r"(d[2]), "+r"(d[3])
        : "r"(a[0]), "r"(a[1]), "r"(a[2]), "r"(a[3]), "r"(b0), "r"(b1));
}
__device__ __forceinline__ void mma_bf16(float* d, const uint32_t* a,
                                         uint32_t b0, uint32_t b1) {
    asm volatile(
        "mma.sync.aligned.m16n8k16.row.col.f32.bf16.bf16.f32 "
        "{%0,%1,%2,%3}, {%4,%5,%6,%7}, {%8,%9}, {%0,%1,%2,%3};"
        : "+f"(d[0]), "+f"(d[1]), "+f"(d[2]), "+f"(d[3])
        : "r"(a[0]), "r"(a[1]), "r"(a[2]), "r"(a[3]), "r"(b0), "r"(b1));
}
__device__ __forceinline__ uint32_t pack2(bf16 a, bf16 b) {
    return (uint32_t)__bfloat16_as_ushort(a) |
           ((uint32_t)__bfloat16_as_ushort(b) << 16);
}
__device__ __forceinline__ uint32_t pack_hilo(float a, float b, uint32_t& lo) {
    bf16 ha = __float2bfloat16(a), hb = __float2bfloat16(b);
    lo = pack2(__float2bfloat16(a - __bfloat162float(ha)),
               __float2bfloat16(b - __bfloat162float(hb)));
    return pack2(ha, hb);
}
__device__ __forceinline__ void quant1(float v, float ip, s8& a1, s8& a0) {
    float x = v * ip;
    float r1 = rintf(x);
    a1 = (s8)(int)r1;
    a0 = (s8)(int)rintf((x - r1) * 254.f);
}
// quantize float4 -> packed (hi, lo) uint32 byte-lanes
__device__ __forceinline__ void quant4(float4 v, float ip, uint32_t& u1, uint32_t& u0) {
    s8 a1[4], a0[4];
    quant1(v.x, ip, a1[0], a0[0]);
    quant1(v.y, ip, a1[1], a0[1]);
    quant1(v.z, ip, a1[2], a0[2]);
    quant1(v.w, ip, a1[3], a0[3]);
    u1 = ((uint32_t)(uint8_t)a1[0]) | ((uint32_t)(uint8_t)a1[1] << 8) |
         ((uint32_t)(uint8_t)a1[2] << 16) | ((uint32_t)(uint8_t)a1[3] << 24);
    u0 = ((uint32_t)(uint8_t)a0[0]) | ((uint32_t)(uint8_t)a0[1] << 8) |
         ((uint32_t)(uint8_t)a0[2] << 16) | ((uint32_t)(uint8_t)a0[3] << 24);
}
__device__ __forceinline__ float blockmax256(float v, float* red) {
    const int tid = threadIdx.x;
#pragma unroll
    for (int o = 16; o >= 1; o >>= 1)
        v = fmaxf(v, __shfl_xor_sync(0xffffffffu, v, o));
    if ((tid & 31) == 0) red[tid >> 5] = v;
    __syncthreads();
    if (tid == 0) {
        float m = red[0];
#pragma unroll
        for (int w = 1; w < 8; w++) m = fmaxf(m, red[w]);
        red[0] = m;
    }
    __syncthreads();
    return red[0];
}

// ---------------------------------------------------------------------------
// Quantization. quant_inputs merges x rows (vectorized) / w_qkv cols / w_o
// cols (strided, scalar) into one launch (grid 7168). quant_ao vectorized.
// ---------------------------------------------------------------------------
__global__ void quant_inputs(const float* __restrict__ x,
                             const float* __restrict__ w_qkv,
                             const float* __restrict__ w_o) {
    __shared__ float red[8];
    const int rb = blockIdx.x, tid = threadIdx.x;
    if (rb < 4096) {                      // x rows: float4 path (192 lanes)
        const int r = rb;
        float4 v = make_float4(0.f, 0.f, 0.f, 0.f);
        float mx = 0.f;
        if (tid < 192) {
            v = *(const float4*)(x + (size_t)r * 768 + tid * 4);
            mx = fmaxf(fmaxf(fabsf(v.x), fabsf(v.y)),
                       fmaxf(fabsf(v.z), fabsf(v.w)));
        }
        mx = fmaxf(blockmax256(mx, red), 1e-20f);
        if (tid == 0) g_sx[r] = mx * (1.f / 127.f);
        if (tid < 192) {
            uint32_t u1, u0;
            quant4(v, 127.f / mx, u1, u0);
            *(uint32_t*)(g_xq1 + (size_t)r * 768 + tid * 4) = u1;
            *(uint32_t*)(g_xq0 + (size_t)r * 768 + tid * 4) = u0;
        }
        return;
    }
    // strided weight paths (scalar, 256 lanes x 3)
    float v[3]; float mx = 0.f;
    s8 *d1, *d0; float* sc; int r;
    if (rb < 6400) {                      // w_qkv cols: r = ha*64 + n
        r = rb - 4096; d1 = g_wq1; d0 = g_wq0; sc = g_swq;
#pragma unroll
        for (int j = 0; j < 3; j++) {
            v[j] = w_qkv[((size_t)(r >> 6) * 768 + tid + j * 256) * 64 + (r & 63)];
            mx = fmaxf(mx, fabsf(v[j]));
        }
    } else {                              // w_o cols
        r = rb - 6400; d1 = g_woq1; d0 = g_woq0; sc = g_swo;
#pragma unroll
        for (int j = 0; j < 3; j++) {
            v[j] = w_o[(size_t)(tid + j * 256) * 768 + r];
            mx = fmaxf(mx, fabsf(v[j]));
        }
    }
    mx = fmaxf(blockmax256(mx, red), 1e-20f);
    if (tid == 0) sc[r] = mx * (1.f / 127.f);
    const float ip = 127.f / mx;
#pragma unroll
    for (int j = 0; j < 3; j++) {
        s8 a1, a0; quant1(v[j], ip, a1, a0);
        d1[(size_t)r * 768 + tid + j * 256] = a1;
        d0[(size_t)r * 768 + tid + j * 256] = a0;
    }
}

__global__ void quant_ao() {
    __shared__ float red[8];
    const int r = blockIdx.x, tid = threadIdx.x;
    float4 v = make_float4(0.f, 0.f, 0.f, 0.f);
    float mx = 0.f;
    if (tid < 192) {
        v = *(const float4*)(g_aof + (size_t)r * 768 + tid * 4);
        mx = fmaxf(fmaxf(fabsf(v.x), fabsf(v.y)),
                   fmaxf(fabsf(v.z), fabsf(v.w)));
    }
    mx = fmaxf(blockmax256(mx, red), 1e-20f);
    if (tid == 0) g_sao[r] = mx * (1.f / 127.f);
    if (tid < 192) {
        uint32_t u1, u0;
        quant4(v, 127.f / mx, u1, u0);
        *(uint32_t*)(g_aoq1 + (size_t)r * 768 + tid * 4) = u1;
        *(uint32_t*)(g_aoq0 + (size_t)r * 768 + tid * 4) = u0;
    }
}

// ---------------------------------------------------------------------------
// int8 GEMM core: D[128x64] = A[128x768] * B[64x768]^T (2-stage cp.async)
// ---------------------------------------------------------------------------
#define QSTG 49152u
#define GEMM_SMEM 98304

__device__ __forceinline__ void i8_load_stage(
    uint32_t sb, int st, const s8* __restrict__ A1, const s8* __restrict__ A0,
    const s8* __restrict__ B1, const s8* __restrict__ B0, int kc)
{
    const uint32_t base = sb + (uint32_t)st * QSTG;
    const int tid = threadIdx.x;
#pragma unroll
    for (int j = 0; j < 8; j++) {
        int i = tid + j * 128;
        int r = i >> 3, c = i & 7;
        uint32_t off = sw128((uint32_t)(r * 128 + c * 16));
        cp16(base + off,          A1 + (size_t)r * 768 + kc + c * 16);
        cp16(base + 16384u + off, A0 + (size_t)r * 768 + kc + c * 16);
    }
#pragma unroll
    for (int j = 0; j < 4; j++) {
        int i = tid + j * 128;
        int r = i >> 3, c = i & 7;
        uint32_t off = sw128((uint32_t)(r * 128 + c * 16));
        cp16(base + 32768u + off, B1 + (size_t)r * 768 + kc + c * 16);
        cp16(base + 40960u + off, B0 + (size_t)r * 768 + kc + c * 16);
    }
}

__device__ __forceinline__ void i8_mma_stage(uint32_t sb, int st,
                                             int I11[2][8][4], int Ix[2][8][4])
{
    const int tid = threadIdx.x, wid = tid >> 5, l = tid & 31;
    const int a_r  = l & 15, a_kb = (l >> 4) * 16;
    const int b_n  = (l & 7) + ((l >> 4) & 1) * 8;
    const int b_kb = ((l >> 3) & 1) * 16;
    const int mb = wid * 32;
    const uint32_t base = sb + (uint32_t)st * QSTG;

#pragma unroll
    for (int kb = 0; kb < 4; kb++) {
        uint32_t A1f[2][4], A0f[2][4];
#pragma unroll
        for (int m = 0; m < 2; m++) {
            uint32_t aa = sw128((uint32_t)((mb + m * 16 + a_r) * 128 + kb * 32 + a_kb));
            ldmx4(A1f[m], base + aa);
            ldmx4(A0f[m], base + 16384u + aa);
        }
#pragma unroll
        for (int bn = 0; bn < 4; bn++) {
            uint32_t B1f[4], B0f[4];
            uint32_t ba = sw128((uint32_t)((bn * 16 + b_n) * 128 + kb * 32 + b_kb));
            ldmx4(B1f, base + 32768u + ba);
            ldmx4(B0f, base + 40960u + ba);
#pragma unroll
            for (int m = 0; m < 2; m++) {
                mma_s8(I11[m][2*bn],   A1f[m], B1f[0], B1f[1]);
                mma_s8(Ix [m][2*bn],   A1f[m], B0f[0], B0f[1]);
                mma_s8(Ix [m][2*bn],   A0f[m], B1f[0], B1f[1]);
                mma_s8(I11[m][2*bn+1], A1f[m], B1f[2], B1f[3]);
                mma_s8(Ix [m][2*bn+1], A1f[m], B0f[2], B0f[3]);
                mma_s8(Ix [m][2*bn+1], A0f[m], B1f[2], B1f[3]);
            }
        }
    }
}

__device__ __forceinline__ void i8_gemm(
    uint32_t sb, const s8* A1, const s8* A0, const s8* B1, const s8* B0,
    int I11[2][8][4], int Ix[2][8][4])
{
    i8_load_stage(sb, 0, A1, A0, B1, B0, 0);
    CP_COMMIT();
    for (int kc = 0; kc < 6; kc++) {
        if (kc + 1 < 6) {
            i8_load_stage(sb, (kc + 1) & 1, A1, A0, B1, B0, (kc + 1) * 128);
            CP_COMMIT();
            CP_WAIT(1);
        } else {
            CP_WAIT(0);
        }
        __syncthreads();
        i8_mma_stage(sb, kc & 1, I11, Ix);
        __syncthreads();
    }
}

// ---------------------------------------------------------------------------
// Kernel 1: QKV projection (int8 math, bf16 hi/lo outputs). grid (16,72).
// ---------------------------------------------------------------------------
__global__ __launch_bounds__(128) void qkv_i8_kernel() {
    extern __shared__ char smc[];
    uint32_t sb = smem_u32(smc);
    const int tid = threadIdx.x, wid = tid >> 5, l = tid & 31;
    const int g = l >> 2, t = l & 3;
    const int mb = wid * 32;

    const int m0 = blockIdx.x * 128;
    const int z = blockIdx.y;
    const int a = z / 24, bh = z % 24;
    const int b = bh / 12, h = bh % 12;

    int I11[2][8][4], Ix[2][8][4];
#pragma unroll
    for (int m = 0; m < 2; m++)
#pragma unroll
        for (int nf = 0; nf < 8; nf++)
#pragma unroll
            for (int e = 0; e < 4; e++) { I11[m][nf][e] = 0; Ix[m][nf][e] = 0; }

    i8_gemm(sb,
            g_xq1 + ((size_t)b * 2048 + m0) * 768,
            g_xq0 + ((size_t)b * 2048 + m0) * 768,
            g_wq1 + (size_t)(h * 3 + a) * 64 * 768,
            g_wq0 + (size_t)(h * 3 + a) * 64 * 768, I11, Ix);

    float sxr[2][2], swc[8][2];
#pragma unroll
    for (int m = 0; m < 2; m++)
#pragma unroll
        for (int rh = 0; rh < 2; rh++)
            sxr[m][rh] = g_sx[b * 2048 + m0 + mb + m * 16 + g + rh * 8];
#pragma unroll
    for (int nf = 0; nf < 8; nf++) {
        swc[nf][0] = g_swq[(h * 3 + a) * 64 + nf * 8 + 2 * t];
        swc[nf][1] = g_swq[(h * 3 + a) * 64 + nf * 8 + 2 * t + 1];
    }
    float d[2][8][4];
#pragma unroll
    for (int m = 0; m < 2; m++)
#pragma unroll
        for (int nf = 0; nf < 8; nf++)
#pragma unroll
            for (int e = 0; e < 4; e++) {
                float f = (float)I11[m][nf][e] + (float)Ix[m][nf][e] * (1.f / 254.f);
                d[m][nf][e] = f * sxr[m][e >> 1] * swc[nf][e & 1];
            }

    if (a < 2) {
        const float sc = (a == 0) ? 0.125f : 1.0f;
        bf16* ohb = (a == 0 ? g_q_hi : g_k_hi) + ((size_t)bh * 2048 + m0) * 64;
        bf16* olb = (a == 0 ? g_q_lo : g_k_lo) + ((size_t)bh * 2048 + m0) * 64;
#pragma unroll
        for (int m = 0; m < 2; m++)
#pragma unroll
            for (int rh = 0; rh < 2; rh++) {
                int row = mb + m * 16 + g + rh * 8;
                uint32_t* ph = (uint32_t*)(ohb + (size_t)row * 64);
                uint32_t* pl = (uint32_t*)(olb + (size_t)row * 64);
#pragma unroll
                for (int nf = 0; nf < 8; nf++) {
                    uint32_t lo;
                    uint32_t hi = pack_hilo(d[m][nf][rh*2] * sc,
                                            d[m][nf][rh*2+1] * sc, lo);
                    ph[nf * 4 + t] = hi;
                    pl[nf * 4 + t] = lo;
                }
            }
    } else {
        // V: stage fp32, write transposed [d][p] bf16 hi/lo
        float* Ssm = (float*)smc;   // [128][68]
        __syncthreads();
#pragma unroll
        for (int m = 0; m < 2; m++)
#pragma unroll
            for (int rh = 0; rh < 2; rh++) {
                int row = mb + m * 16 + g + rh * 8;
#pragma unroll
                for (int nf = 0; nf < 8; nf++) {
                    Ssm[row * 68 + nf * 8 + 2 * t]     = d[m][nf][rh * 2];
                    Ssm[row * 68 + nf * 8 + 2 * t + 1] = d[m][nf][rh * 2 + 1];
                }
            }
        __syncthreads();
        for (int idx = tid; idx < 64 * 128; idx += 128) {
            int dd = idx >> 7, p = idx & 127;
            float v = Ssm[p * 68 + dd];
            bf16 hv = __float2bfloat16(v);
            size_t go = ((size_t)bh * 64 + dd) * 2048 + m0 + p;
            g_vt_hi[go] = hv;
            g_vt_lo[go] = __float2bfloat16(v - __bfloat162float(hv));
        }
    }
}

// ---------------------------------------------------------------------------
// Kernel 2: flash attention, bf16 3-term (R13 exact). grid (16, 24), 128 thr.
// smem: QH 0 (16K), QL 16384; stages at 32768 + st*32768:
//       KH +0, KL +8192, VH +16384, VL +24576.  total 96K.
// ---------------------------------------------------------------------------
#define ASTAGE_BASE 32768u
#define ASTAGE      32768u
#define ATTN_SMEM   98304

__device__ __forceinline__ void attn_load_stage(uint32_t sb, int st, int bh, int k0) {
    const uint32_t base = sb + ASTAGE_BASE + (uint32_t)st * ASTAGE;
    const int tid = threadIdx.x;
    const bf16* kh = g_k_hi + ((size_t)bh * 2048 + k0) * 64;
    const bf16* kl = g_k_lo + ((size_t)bh * 2048 + k0) * 64;
    const bf16* vh = g_vt_hi + (size_t)bh * 64 * 2048 + k0;
    const bf16* vl = g_vt_lo + (size_t)bh * 64 * 2048 + k0;
#pragma unroll
    for (int j = 0; j < 4; j++) {
        int i = tid + j * 128;
        int r = i >> 3, c = i & 7;
        uint32_t off = sw128((uint32_t)(r * 128 + c * 16));
        cp16(base + off,          kh + (size_t)r * 64 + c * 8);
        cp16(base + 8192u + off,  kl + (size_t)r * 64 + c * 8);
        cp16(base + 16384u + off, vh + (size_t)r * 2048 + c * 8);
        cp16(base + 24576u + off, vl + (size_t)r * 2048 + c * 8);
    }
}

__global__ __launch_bounds__(128) void attn_mma_kernel() {
    extern __shared__ char smc[];
    uint32_t sb = smem_u32(smc);
    const int tid = threadIdx.x, wid = tid >> 5, l = tid & 31;
    const int g = l >> 2, t = l & 3;
    const int a_r  = l & 15;
    const int a_kb = (l >> 4) * 16;
    const int b_n  = (l & 7) + ((l >> 4) & 1) * 8;
    const int b_kb = ((l >> 3) & 1) * 16;
    const int mb = wid * 32;

    const int bh = blockIdx.y;
    const int q0 = blockIdx.x * 128;

    {
        const bf16* qh = g_q_hi + ((size_t)bh * 2048 + q0) * 64;
        const bf16* ql = g_q_lo + ((size_t)bh * 2048 + q0) * 64;
#pragma unroll
        for (int j = 0; j < 8; j++) {
            int i = tid + j * 128;
            int r = i >> 3, c = i & 7;
            uint32_t off = sw128((uint32_t)(r * 128 + c * 16));
            cp16(sb + off,          qh + (size_t)r * 64 + c * 8);
            cp16(sb + 16384u + off, ql + (size_t)r * 64 + c * 8);
        }
    }
    attn_load_stage(sb, 0, bh, 0);
    CP_COMMIT();

    float o[2][8][4];
    float lacc[2][2];
#pragma unroll
    for (int m = 0; m < 2; m++) {
        lacc[m][0] = lacc[m][1] = 0.f;
#pragma unroll
        for (int nf = 0; nf < 8; nf++)
#pragma unroll
            for (int e = 0; e < 4; e++) o[m][nf][e] = 0.f;
    }

    for (int kt = 0; kt < 32; kt++) {
        if (kt + 1 < 32) {
            attn_load_stage(sb, (kt + 1) & 1, bh, (kt + 1) * 64);
            CP_COMMIT();
            CP_WAIT(1);
        } else {
            CP_WAIT(0);
        }
        __syncthreads();
        const uint32_t kb = sb + ASTAGE_BASE + (uint32_t)(kt & 1) * ASTAGE;

        float s[2][8][4];
#pragma unroll
        for (int m = 0; m < 2; m++)
#pragma unroll
            for (int nf = 0; nf < 8; nf++)
#pragma unroll
                for (int e = 0; e < 4; e++) s[m][nf][e] = 0.f;

#pragma unroll
        for (int ks = 0; ks < 4; ks++) {
            const int k0b = ks * 32;
            uint32_t Bh[4][4], Bl[4][4];
#pragma unroll
            for (int bn = 0; bn < 4; bn++) {
                uint32_t ba = sw128((uint32_t)((bn * 16 + b_n) * 128 + k0b + b_kb));
                ldmx4(Bh[bn], kb + ba);
                ldmx4(Bl[bn], kb + 8192u + ba);
            }
#pragma unroll
            for (int m = 0; m < 2; m++) {
                uint32_t Ah[4], Al[4];
                uint32_t aa = sw128((uint32_t)((mb + m * 16 + a_r) * 128 + k0b + a_kb));
                ldmx4(Ah, sb + aa);
                ldmx4(Al, sb + 16384u + aa);
#pragma unroll
                for (int bn = 0; bn < 4; bn++) {
                    mma_bf16(s[m][2*bn],   Ah, Bh[bn][0], Bh[bn][1]);
                    mma_bf16(s[m][2*bn],   Ah, Bl[bn][0], Bl[bn][1]);
                    mma_bf16(s[m][2*bn],   Al, Bh[bn][0], Bh[bn][1]);
                    mma_bf16(s[m][2*bn+1], Ah, Bh[bn][2], Bh[bn][3]);
                    mma_bf16(s[m][2*bn+1], Ah, Bl[bn][2], Bl[bn][3]);
                    mma_bf16(s[m][2*bn+1], Al, Bh[bn][2], Bh[bn][3]);
                }
            }
        }

        uint32_t ph[2][4][4], pl[2][4][4];
#pragma unroll
        for (int m = 0; m < 2; m++) {
            float r0 = 0.f, r1 = 0.f;
#pragma unroll
            for (int nf = 0; nf < 8; nf++) {
                s[m][nf][0] = __expf(s[m][nf][0]);
                s[m][nf][1] = __expf(s[m][nf][1]);
                s[m][nf][2] = __expf(s[m][nf][2]);
                s[m][nf][3] = __expf(s[m][nf][3]);
                r0 += s[m][nf][0] + s[m][nf][1];
                r1 += s[m][nf][2] + s[m][nf][3];
            }
            r0 += __shfl_xor_sync(0xffffffffu, r0, 1);
            r0 += __shfl_xor_sync(0xffffffffu, r0, 2);
            r1 += __shfl_xor_sync(0xffffffffu, r1, 1);
            r1 += __shfl_xor_sync(0xffffffffu, r1, 2);
            lacc[m][0] += r0;
            lacc[m][1] += r1;
#pragma unroll
            for (int ks = 0; ks < 4; ks++) {
                ph[m][ks][0] = pack_hilo(s[m][2*ks][0],   s[m][2*ks][1],   pl[m][ks][0]);
                ph[m][ks][1] = pack_hilo(s[m][2*ks][2],   s[m][2*ks][3],   pl[m][ks][1]);
                ph[m][ks][2] = pack_hilo(s[m][2*ks+1][0], s[m][2*ks+1][1], pl[m][ks][2]);
                ph[m][ks][3] = pack_hilo(s[m][2*ks+1][2], s[m][2*ks+1][3], pl[m][ks][3]);
            }
        }

#pragma unroll
        for (int ks = 0; ks < 4; ks++) {
            const int k0b = ks * 32;
            uint32_t Vh[4][4], Vl[4][4];
#pragma unroll
            for (int bn = 0; bn < 4; bn++) {
                uint32_t ba = sw128((uint32_t)((bn * 16 + b_n) * 128 + k0b + b_kb));
                ldmx4(Vh[bn], kb + 16384u + ba);
                ldmx4(Vl[bn], kb + 24576u + ba);
            }
#pragma unroll
            for (int m = 0; m < 2; m++)
#pragma unroll
                for (int bn = 0; bn < 4; bn++) {
                    mma_bf16(o[m][2*bn],   ph[m][ks], Vh[bn][0], Vh[bn][1]);
                    mma_bf16(o[m][2*bn],   ph[m][ks], Vl[bn][0], Vl[bn][1]);
                    mma_bf16(o[m][2*bn],   pl[m][ks], Vh[bn][0], Vh[bn][1]);
                    mma_bf16(o[m][2*bn+1], ph[m][ks], Vh[bn][2], Vh[bn][3]);
                    mma_bf16(o[m][2*bn+1], ph[m][ks], Vl[bn][2], Vl[bn][3]);
                    mma_bf16(o[m][2*bn+1], pl[m][ks], Vh[bn][2], Vh[bn][3]);
                }
        }
        __syncthreads();
    }

    // epilogue: normalize, write fp32 g_aof
    const int b = bh / 12, h = bh % 12;
#pragma unroll
    for (int m = 0; m < 2; m++)
#pragma unroll
        for (int rh = 0; rh < 2; rh++) {
            float inv = 1.f / lacc[m][rh];
            int row = mb + m * 16 + g + rh * 8;
            float* op = g_aof + (size_t)(b * 2048 + q0 + row) * 768 + h * 64;
#pragma unroll
            for (int nf = 0; nf < 8; nf++) {
                float2 v = make_float2(o[m][nf][rh*2] * inv, o[m][nf][rh*2+1] * inv);
                *(float2*)(op + nf * 8 + 2 * t) = v;
            }
        }
}

// ---------------------------------------------------------------------------
// Kernel 3: output projection int8. grid = (32, 12), 128 threads.
// ---------------------------------------------------------------------------
__global__ __launch_bounds__(128) void proj_i8_kernel(float* __restrict__ out) {
    extern __shared__ char smc[];
    uint32_t sb = smem_u32(smc);
    const int tid = threadIdx.x, wid = tid >> 5, l = tid & 31;
    const int g = l >> 2, t = l & 3;
    const int mb = wid * 32;
    const int m0 = blockIdx.x * 128;
    const int n0 = blockIdx.y * 64;

    int I11[2][8][4], Ix[2][8][4];
#pragma unroll
    for (int m = 0; m < 2; m++)
#pragma unroll
        for (int nf = 0; nf < 8; nf++)
#pragma unroll
            for (int e = 0; e < 4; e++) { I11[m][nf][e] = 0; Ix[m][nf][e] = 0; }

    i8_gemm(sb,
            g_aoq1 + (size_t)m0 * 768, g_aoq0 + (size_t)m0 * 768,
            g_woq1 + (size_t)n0 * 768, g_woq0 + (size_t)n0 * 768, I11, Ix);

    float sar[2][2], swc[8][2];
#pragma unroll
    for (int m = 0; m < 2; m++)
#pragma unroll
        for (int rh = 0; rh < 2; rh++)
            sar[m][rh] = g_sao[m0 + mb + m * 16 + g + rh * 8];
#pragma unroll
    for (int nf = 0; nf < 8; nf++) {
        swc[nf][0] = g_swo[n0 + nf * 8 + 2 * t];
        swc[nf][1] = g_swo[n0 + nf * 8 + 2 * t + 1];
    }
#pragma unroll
    for (int m = 0; m < 2; m++)
#pragma unroll
        for (int rh = 0; rh < 2; rh++) {
            int row = mb + m * 16 + g + rh * 8;
            float* op = out + (size_t)(m0 + row) * 768 + n0;
#pragma unroll
            for (int nf = 0; nf < 8; nf++) {
                float f0 = (float)I11[m][nf][rh*2]   + (float)Ix[m][nf][rh*2]   * (1.f/254.f);
                float f1 = (float)I11[m][nf][rh*2+1] + (float)Ix[m][nf][rh*2+1] * (1.f/254.f);
                float2 v = make_float2(f0 * sar[m][rh] * swc[nf][0],
                                       f1 * sar[m][rh] * swc[nf][1]);
                *(float2*)(op + nf * 8 + 2 * t) = v;
            }
        }
}

// ---------------------------------------------------------------------------
extern "C" void kernel_launch(void* const* d_in, const int* in_sizes, int n_in,
                              void* d_out, int out_size)
{
    const float* x = nullptr;
    const float* w_qkv = nullptr;
    const float* w_o = nullptr;
    for (int i = 0; i < n_in; i++) {
        if (in_sizes[i] == 3145728)      x     = (const float*)d_in[i];
        else if (in_sizes[i] == 1769472) w_qkv = (const float*)d_in[i];
        else if (in_sizes[i] == 589824)  w_o   = (const float*)d_in[i];
    }
    float* out = (float*)d_out;

    cudaFuncSetAttribute(qkv_i8_kernel,
                         cudaFuncAttributeMaxDynamicSharedMemorySize, GEMM_SMEM);
    cudaFuncSetAttribute(attn_mma_kernel,
                         cudaFuncAttributeMaxDynamicSharedMemorySize, ATTN_SMEM);
    cudaFuncSetAttribute(proj_i8_kernel,
                         cudaFuncAttributeMaxDynamicSharedMemorySize, GEMM_SMEM);

    quant_inputs<<<7168, 256>>>(x, w_qkv, w_o);
    qkv_i8_kernel<<<dim3(16, 72), 128, GEMM_SMEM>>>();
    attn_mma_kernel<<<dim3(16, 24), 128, ATTN_SMEM>>>();
    quant_ao<<<4096, 256>>>();
    proj_i8_kernel<<<dim3(32, 12), 128, GEMM_SMEM>>>(out);
}